// round 14
// baseline (speedup 1.0000x reference)
#include <cuda_runtime.h>
#include <cuda_bf16.h>
#include <cstdint>

#define L_SEQ 1024
#define HID   2048
#define NH    32
#define HD    64
#define FD    64
#define NC    16
#define CS    64
#define GK    2048
#define GN    2048
#define PLANE (L_SEQ * HID)

// ---------------- scratch (device globals: no allocation allowed) ----------------
__device__ float g_FQ[NH * L_SEQ * FD];
__device__ float g_FK[NH * L_SEQ * FD];
__device__ float g_V [PLANE];       // combined V (written by featsum)
__device__ float g_S [NH * NC * FD * HD];
__device__ float g_KS[NH * NC * FD];
__device__ float g_P [9 * PLANE];   // QKV split-K3 partials
__device__ float g_PO[2 * PLANE];   // Wo split-K2 partials

__device__ __nv_bfloat16 g_Xhi [PLANE];
__device__ __nv_bfloat16 g_Xlo [PLANE];
__device__ __nv_bfloat16 g_Wqhi[HID * HID];
__device__ __nv_bfloat16 g_Wqlo[HID * HID];
__device__ __nv_bfloat16 g_Wkhi[HID * HID];
__device__ __nv_bfloat16 g_Wklo[HID * HID];
__device__ __nv_bfloat16 g_Wvhi[HID * HID];
__device__ __nv_bfloat16 g_Wvlo[HID * HID];
__device__ __nv_bfloat16 g_Wohi[HID * HID];
__device__ __nv_bfloat16 g_Wolo[HID * HID];
__device__ __nv_bfloat16 g_Yhi [PLANE];
__device__ __nv_bfloat16 g_Ylo [PLANE];

// =============================== helpers ==========================================
__device__ __forceinline__ uint32_t smem_u32(const void* p) {
    uint32_t a;
    asm("{ .reg .u64 t; cvta.to.shared.u64 t, %1; cvt.u32.u64 %0, t; }" : "=r"(a) : "l"(p));
    return a;
}
__device__ __forceinline__ void ldsm4(uint32_t& r0, uint32_t& r1, uint32_t& r2, uint32_t& r3,
                                      uint32_t addr) {
    asm volatile("ldmatrix.sync.aligned.m8n8.x4.shared.b16 {%0,%1,%2,%3}, [%4];"
                 : "=r"(r0), "=r"(r1), "=r"(r2), "=r"(r3) : "r"(addr));
}
__device__ __forceinline__ void mma16816(float* c, const uint32_t* a, const uint32_t* b) {
    asm volatile(
        "mma.sync.aligned.m16n8k16.row.col.f32.bf16.bf16.f32 "
        "{%0,%1,%2,%3}, {%4,%5,%6,%7}, {%8,%9}, {%0,%1,%2,%3};"
        : "+f"(c[0]), "+f"(c[1]), "+f"(c[2]), "+f"(c[3])
        : "r"(a[0]), "r"(a[1]), "r"(a[2]), "r"(a[3]), "r"(b[0]), "r"(b[1]));
}
#define CP16(dst, src) \
    asm volatile("cp.async.cg.shared.global [%0], [%1], 16;" :: "r"(dst), "l"(src) : "memory")

__device__ __forceinline__ void split4(float4 v, uint2& hp, uint2& lp) {
    __nv_bfloat16 h0 = __float2bfloat16_rn(v.x);
    __nv_bfloat16 h1 = __float2bfloat16_rn(v.y);
    __nv_bfloat16 h2 = __float2bfloat16_rn(v.z);
    __nv_bfloat16 h3 = __float2bfloat16_rn(v.w);
    __nv_bfloat16 l0 = __float2bfloat16_rn(v.x - __bfloat162float(h0));
    __nv_bfloat16 l1 = __float2bfloat16_rn(v.y - __bfloat162float(h1));
    __nv_bfloat16 l2 = __float2bfloat16_rn(v.z - __bfloat162float(h2));
    __nv_bfloat16 l3 = __float2bfloat16_rn(v.w - __bfloat162float(h3));
    hp.x = (uint32_t)__bfloat16_as_ushort(h0) | ((uint32_t)__bfloat16_as_ushort(h1) << 16);
    hp.y = (uint32_t)__bfloat16_as_ushort(h2) | ((uint32_t)__bfloat16_as_ushort(h3) << 16);
    lp.x = (uint32_t)__bfloat16_as_ushort(l0) | ((uint32_t)__bfloat16_as_ushort(l1) << 16);
    lp.y = (uint32_t)__bfloat16_as_ushort(l2) | ((uint32_t)__bfloat16_as_ushort(l3) << 16);
}

__device__ __forceinline__ void split8_store(const float* s, __nv_bfloat16* hi,
                                             __nv_bfloat16* lo, long loc) {
    float4 v0 = *(const float4*)(s + loc);
    float4 v1 = *(const float4*)(s + loc + 4);
    uint2 h0, l0, h1, l1;
    split4(v0, h0, l0);
    split4(v1, h1, l1);
    uint4 ho, lv;
    ho.x = h0.x; ho.y = h0.y; ho.z = h1.x; ho.w = h1.y;
    lv.x = l0.x; lv.y = l0.y; lv.z = l1.x; lv.w = l1.y;
    *(uint4*)(hi + loc) = ho;
    *(uint4*)(lo + loc) = lv;
}

// ---------------- fused split: X + 4 weights in one launch ------------------------
__global__ __launch_bounds__(256) void split_all(
    const float* __restrict__ X,  const float* __restrict__ Wq,
    const float* __restrict__ Wk, const float* __restrict__ Wv,
    const float* __restrict__ Wo,
    __nv_bfloat16* __restrict__ Xhi, __nv_bfloat16* __restrict__ Xlo,
    __nv_bfloat16* __restrict__ Wqh, __nv_bfloat16* __restrict__ Wql,
    __nv_bfloat16* __restrict__ Wkh, __nv_bfloat16* __restrict__ Wkl,
    __nv_bfloat16* __restrict__ Wvh, __nv_bfloat16* __restrict__ Wvl,
    __nv_bfloat16* __restrict__ Woh, __nv_bfloat16* __restrict__ Wol) {
    long off = ((long)blockIdx.x * 256 + threadIdx.x) * 8;
    const float* s;
    __nv_bfloat16 *hi, *lo;
    long loc;
    const long W = (long)HID * HID;
    if (off < PLANE)            { s = X;  hi = Xhi; lo = Xlo; loc = off; }
    else if (off < PLANE + W)   { s = Wq; hi = Wqh; lo = Wql; loc = off - PLANE; }
    else if (off < PLANE + 2*W) { s = Wk; hi = Wkh; lo = Wkl; loc = off - PLANE - W; }
    else if (off < PLANE + 3*W) { s = Wv; hi = Wvh; lo = Wvl; loc = off - PLANE - 2*W; }
    else                        { s = Wo; hi = Woh; lo = Wol; loc = off - PLANE - 3*W; }
    split8_store(s, hi, lo, loc);
}

// ---------------- combine for Wo split-K ------------------------------------------
__global__ __launch_bounds__(256) void combine1(const float4* __restrict__ a,
                                                const float4* __restrict__ b,
                                                float4* __restrict__ dst) {
    int i = blockIdx.x * 256 + threadIdx.x;
    float4 va = a[i], vb = b[i];
    dst[i] = make_float4(va.x + vb.x, va.y + vb.y, va.z + vb.z, va.w + vb.w);
}

// ======= bf16x3 HMMA GEMM: 128x128x32 tile, 2-stage cp.async, split-K(gridDim.z) ==
#define ROWB   80
#define TILEB  (128 * ROWB)
#define STAGEB (4 * TILEB)
#define GEMM_SMEM (2 * STAGEB)

__device__ __forceinline__ void issue_chunk(
    uint32_t stg, const __nv_bfloat16* Ahi, const __nv_bfloat16* Alo,
    const __nv_bfloat16* Bhi, const __nv_bfloat16* Blo,
    int m0, int n0, int k0, int t) {
#pragma unroll
    for (int j = 0; j < 2; j++) {
        int idx = t + 256 * j;
        int row = idx >> 2, c = idx & 3;
        uint32_t dof = (uint32_t)(row * ROWB + c * 16);
        long aoff = (long)(m0 + row) * GK + k0 + c * 8;
        long boff = (long)(n0 + row) * GK + k0 + c * 8;
        CP16(stg + dof,             Ahi + aoff);
        CP16(stg + TILEB + dof,     Alo + aoff);
        CP16(stg + 2 * TILEB + dof, Bhi + boff);
        CP16(stg + 3 * TILEB + dof, Blo + boff);
    }
    asm volatile("cp.async.commit_group;" ::: "memory");
}

__global__ __launch_bounds__(256, 2) void gemm_bf16x3(
    const __nv_bfloat16* __restrict__ Ahi, const __nv_bfloat16* __restrict__ Alo,
    const __nv_bfloat16* __restrict__ Bhi0, const __nv_bfloat16* __restrict__ Blo0,
    const __nv_bfloat16* __restrict__ Bhi1, const __nv_bfloat16* __restrict__ Blo1,
    const __nv_bfloat16* __restrict__ Bhi2, const __nv_bfloat16* __restrict__ Blo2,
    float* __restrict__ Pout) {
    extern __shared__ char smem[];
    const uint32_t sb = smem_u32(smem);

    const int t = threadIdx.x, wid = t >> 5, lane = t & 31;
    const int wsel  = blockIdx.x >> 4;
    const int kslot = blockIdx.z;
    const int nz    = gridDim.z;
    const int n0 = (blockIdx.x & 15) * 128;
    const int m0 = blockIdx.y * 128;
    const __nv_bfloat16* Bhi = (wsel == 0) ? Bhi0 : (wsel == 1) ? Bhi1 : Bhi2;
    const __nv_bfloat16* Blo = (wsel == 0) ? Blo0 : (wsel == 1) ? Blo1 : Blo2;
    float* C = Pout + (long)(wsel * nz + kslot) * PLANE;

    const int per = 64 / nz, rem = 64 % nz;
    const int cstart = kslot * per + (kslot < rem ? kslot : rem);
    const int NIT    = per + (kslot < rem ? 1 : 0);
    const int kb     = cstart * 32;

    const int wm0 = (wid >> 2) * 64;
    const int wn0 = (wid & 3) * 32;
    const int g  = lane >> 3;
    const int lr = lane & 7;

    float acc[4][4][4];
#pragma unroll
    for (int i = 0; i < 4; i++)
#pragma unroll
        for (int j = 0; j < 4; j++)
#pragma unroll
            for (int k = 0; k < 4; k++) acc[i][j][k] = 0.f;

    issue_chunk(sb,          Ahi, Alo, Bhi, Blo, m0, n0, kb,      t);
    issue_chunk(sb + STAGEB, Ahi, Alo, Bhi, Blo, m0, n0, kb + 32, t);

    for (int it = 0; it < NIT; it++) {
        if (it < NIT - 1) asm volatile("cp.async.wait_group 1;" ::: "memory");
        else              asm volatile("cp.async.wait_group 0;" ::: "memory");
        __syncthreads();

        const uint32_t ahi = sb + (it & 1) * STAGEB;
        const uint32_t alo = ahi + TILEB;
        const uint32_t bhi = ahi + 2 * TILEB;
        const uint32_t blo = ahi + 3 * TILEB;

#pragma unroll
        for (int ks = 0; ks < 2; ks++) {
            uint32_t bh[4][2], bl[4][2];
#pragma unroll
            for (int nt2 = 0; nt2 < 2; nt2++) {
                int row = wn0 + nt2 * 16 + (g >> 1) * 8 + lr;
                int kc  = ks * 16 + (g & 1) * 8;
                uint32_t off = (uint32_t)(row * ROWB + kc * 2);
                ldsm4(bh[nt2 * 2][0], bh[nt2 * 2][1], bh[nt2 * 2 + 1][0], bh[nt2 * 2 + 1][1],
                      bhi + off);
                ldsm4(bl[nt2 * 2][0], bl[nt2 * 2][1], bl[nt2 * 2 + 1][0], bl[nt2 * 2 + 1][1],
                      blo + off);
            }
#pragma unroll
            for (int mt = 0; mt < 4; mt++) {
                int row = wm0 + mt * 16 + (g & 1) * 8 + lr;
                int kc  = ks * 16 + (g >> 1) * 8;
                uint32_t off = (uint32_t)(row * ROWB + kc * 2);
                uint32_t ah[4], al[4];
                ldsm4(ah[0], ah[1], ah[2], ah[3], ahi + off);
                ldsm4(al[0], al[1], al[2], al[3], alo + off);
#pragma unroll
                for (int nt = 0; nt < 4; nt++) mma16816(acc[mt][nt], ah, bh[nt]);
#pragma unroll
                for (int nt = 0; nt < 4; nt++) mma16816(acc[mt][nt], ah, bl[nt]);
#pragma unroll
                for (int nt = 0; nt < 4; nt++) mma16816(acc[mt][nt], al, bh[nt]);
            }
        }
        __syncthreads();
        if (it + 2 < NIT)
            issue_chunk(sb + (it & 1) * STAGEB, Ahi, Alo, Bhi, Blo, m0, n0,
                        kb + (it + 2) * 32, t);
    }

    const int gid = lane >> 2, tig = lane & 3;
#pragma unroll
    for (int mt = 0; mt < 4; mt++) {
#pragma unroll
        for (int nt = 0; nt < 4; nt++) {
            int row = m0 + wm0 + mt * 16 + gid;
            int col = n0 + wn0 + nt * 8 + tig * 2;
            *(float2*)(C + (long)row * GN + col) =
                make_float2(acc[mt][nt][0], acc[mt][nt][1]);
            *(float2*)(C + (long)(row + 8) * GN + col) =
                make_float2(acc[mt][nt][2], acc[mt][nt][3]);
        }
    }
}

// ===== fused feature+chunksum per (chunk, head); also writes combined V ===========
#define FS_SMEM ((4096 + 4352 + 4096) * 4)

__device__ __forceinline__ void fs_feature_phase(
    float* qs, float* wt, float* fks, const float* p0, const float* p1, const float* p2,
    const float* Wf, float* dst_g, int l0, int h, int t, bool keep) {
#pragma unroll
    for (int r = 0; r < 16; r++) {
        int e = t + 256 * r;
        int row = e >> 6, col = e & 63;
        long idx = (long)(l0 + row) * HID + h * HD + col;
        qs[e] = p0[idx] + p1[idx] + p2[idx];
        wt[col * 68 + row] = Wf[e];
    }
    __syncthreads();

    int warp = t >> 5, lane = t & 31;
    float z0[8], z1[8];
#pragma unroll
    for (int r = 0; r < 8; r++) { z0[r] = 0.f; z1[r] = 0.f; }
#pragma unroll 4
    for (int d4 = 0; d4 < 64; d4 += 4) {
        float4 qv[8];
#pragma unroll
        for (int r = 0; r < 8; r++)
            qv[r] = *(const float4*)&qs[(warp * 8 + r) * 64 + d4];
        float4 w0v = *(const float4*)&wt[lane * 68 + d4];
        float4 w1v = *(const float4*)&wt[(lane + 32) * 68 + d4];
#pragma unroll
        for (int j = 0; j < 4; j++) {
            float w0 = (&w0v.x)[j];
            float w1 = (&w1v.x)[j];
#pragma unroll
            for (int r = 0; r < 8; r++) {
                float qj = (&qv[r].x)[j];
                z0[r] += qj * w0;
                z1[r] += qj * w1;
            }
        }
    }
#pragma unroll
    for (int r = 0; r < 8; r++) {
        float m = fmaxf(z0[r], z1[r]);
#pragma unroll
        for (int o = 16; o > 0; o >>= 1) m = fmaxf(m, __shfl_xor_sync(0xffffffffu, m, o));
        float e0 = expf(z0[r] - m), e1 = expf(z1[r] - m);
        float s = e0 + e1;
#pragma unroll
        for (int o = 16; o > 0; o >>= 1) s += __shfl_xor_sync(0xffffffffu, s, o);
        float inv = 1.f / s;
        int lr2 = warp * 8 + r;
        float f0 = e0 * inv, f1 = e1 * inv;
        dst_g[(long)(l0 + lr2) * FD + lane]      = f0;
        dst_g[(long)(l0 + lr2) * FD + lane + 32] = f1;
        if (keep) {
            fks[lr2 * 64 + lane]      = f0;
            fks[lr2 * 64 + lane + 32] = f1;
        }
    }
}

__global__ __launch_bounds__(256) void featsum_kernel(
    const float* __restrict__ P,
    const float* __restrict__ Wfq, const float* __restrict__ Wfk,
    float* __restrict__ FQ, float* __restrict__ FK, float* __restrict__ Vc,
    float* __restrict__ S, float* __restrict__ KS) {
    extern __shared__ float sm[];
    float* qs  = sm;
    float* wt  = sm + 4096;
    float* fks = sm + 4096 + 4352;

    int c = blockIdx.x, h = blockIdx.y;
    int l0 = c * CS;
    int t = threadIdx.x;

    fs_feature_phase(qs, wt, fks, P, P + PLANE, P + 2L * PLANE,
                     Wfq + (long)h * HD * FD, FQ + (long)h * L_SEQ * FD, l0, h, t, false);
    __syncthreads();

    fs_feature_phase(qs, wt, fks, P + 3L * PLANE, P + 4L * PLANE, P + 5L * PLANE,
                     Wfk + (long)h * HD * FD, FK + (long)h * L_SEQ * FD, l0, h, t, true);
    __syncthreads();

    // phase V: combine partials into qs, write combined V, then S/KS
    const float* v0 = P + 6L * PLANE;
    const float* v1 = v0 + PLANE;
    const float* v2 = v1 + PLANE;
#pragma unroll
    for (int r = 0; r < 16; r++) {
        int e = t + 256 * r;
        int row = e >> 6, col = e & 63;
        long vi = (long)(l0 + row) * HID + h * HD + col;
        float vv = v0[vi] + v1[vi] + v2[vi];
        qs[e] = vv;
        Vc[vi] = vv;
    }
    __syncthreads();

    int d = t & 63, fg = t >> 6;
    float acc[16];
#pragma unroll
    for (int ff = 0; ff < 16; ff++) acc[ff] = 0.f;
    for (int l = 0; l < 64; l++) {
        float vv = qs[l * 64 + d];
#pragma unroll
        for (int ff = 0; ff < 16; ff++)
            acc[ff] += fks[l * 64 + fg * 16 + ff] * vv;
    }
    float* Sout = S + (long)(h * NC + c) * (FD * HD);
#pragma unroll
    for (int ff = 0; ff < 16; ff++)
        Sout[(fg * 16 + ff) * 64 + d] = acc[ff];

    if (t < 64) {
        float s = 0.f;
        for (int l = 0; l < 64; l++) s += fks[l * 64 + t];
        KS[(long)(h * NC + c) * FD + t] = s;
    }
}

// ---------------- exclusive prefix over chunks ------------------------------------
__global__ __launch_bounds__(256) void prefix_kernel(float* __restrict__ S,
                                                     float* __restrict__ KS) {
    int id = blockIdx.x * 256 + threadIdx.x;
    int h = id >> 12, e = id & 4095;
    float* base = S + (long)h * (NC * FD * HD) + e;
    float v[NC];
#pragma unroll
    for (int c = 0; c < NC; c++) v[c] = base[c * (FD * HD)];
    float run = 0.f;
#pragma unroll
    for (int c = 0; c < NC; c++) { float tmp = v[c]; base[c * (FD * HD)] = run; run += tmp; }

    if (id < NH * FD) {
        int h2 = id >> 6, f = id & 63;
        float* kb = KS + (long)h2 * (NC * FD) + f;
        float kv[NC];
#pragma unroll
        for (int c = 0; c < NC; c++) kv[c] = kb[c * FD];
        float kr = 0.f;
#pragma unroll
        for (int c = 0; c < NC; c++) { float tmp = kv[c]; kb[c * FD] = kr; kr += tmp; }
    }
}

// ---------------- per-chunk output (reads combined V, writes split Y) -------------
__global__ __launch_bounds__(256) void chunkout_kernel(
    const float* __restrict__ FQ, const float* __restrict__ FK,
    const float* __restrict__ V, const float* __restrict__ S,
    const float* __restrict__ KS,
    __nv_bfloat16* __restrict__ Yhi, __nv_bfloat16* __restrict__ Ylo) {
    __shared__ float fqT[4096];
    __shared__ float buf[4096];
    __shared__ float At[4096];

    int c = blockIdx.x, h = blockIdx.y;
    int t = threadIdx.x, lane = t & 31;

    const float* fqg = FQ + (long)(h * L_SEQ + c * CS) * FD;
    const float* fkg = FK + (long)(h * L_SEQ + c * CS) * FD;

#pragma unroll
    for (int r = 0; r < 16; r++) {
        int e = t + 256 * r;
        int i = e >> 6, f = e & 63;
        fqT[f * 64 + (i ^ f)] = fqg[e];
        buf[f * 64 + (i ^ f)] = fkg[e];
    }
    __syncthreads();

    {
        int i = t & 63, jg = t >> 6;
        float a[16];
#pragma unroll
        for (int jj = 0; jj < 16; jj++) a[jj] = 0.f;
        for (int f = 0; f < 64; f++) {
            float qv = fqT[f * 64 + (i ^ f)];
#pragma unroll
            for (int jj = 0; jj < 16; jj++) {
                int j = jg * 16 + jj;
                a[jj] += qv * buf[f * 64 + (j ^ f)];
            }
        }
#pragma unroll
        for (int jj = 0; jj < 16; jj++) {
            int j = jg * 16 + jj;
            At[j * 64 + i] = (j <= i) ? a[jj] : 0.f;
        }
    }
    __syncthreads();

    const float* vg = V + (long)(c * CS) * HID + h * HD;
#pragma unroll
    for (int r = 0; r < 16; r++) {
        int e = t + 256 * r;
        int j = e >> 6, d = e & 63;
        buf[e] = vg[(long)j * HID + d];
    }
    __syncthreads();

    int d = t & 63, ig = t >> 6;
    float y[16];
#pragma unroll
    for (int ii = 0; ii < 16; ii++) y[ii] = 0.f;
    for (int j = 0; j < 64; j++) {
        float vv = buf[j * 64 + d];
#pragma unroll
        for (int ii = 0; ii < 16; ii++)
            y[ii] += At[j * 64 + ig * 16 + ii] * vv;
    }
    float ds = 0.f;
    if (t < 64) {
        ds = 1e-12f;
        const float* kb = KS + (long)(h * NC + c) * FD;
        float kp0 = kb[lane], kp1 = kb[lane + 32];
        for (int f = 0; f < 32; f++) {
            ds += fqT[f * 64 + (t ^ f)] * __shfl_sync(0xffffffffu, kp0, f);
            ds += fqT[(f + 32) * 64 + (t ^ (f + 32))] * __shfl_sync(0xffffffffu, kp1, f);
        }
        for (int j = 0; j < 64; j++) ds += At[j * 64 + t];
    }
    __syncthreads();

    const float* sg = S + (long)(h * NC + c) * (FD * HD);
#pragma unroll
    for (int r = 0; r < 16; r++) {
        int e = t + 256 * r;
        buf[e] = sg[e];
    }
    if (t < 64) At[t] = ds;
    __syncthreads();

    for (int f = 0; f < 64; f++) {
        float kvv = buf[f * 64 + d];
#pragma unroll
        for (int ii = 0; ii < 16; ii++)
            y[ii] += fqT[f * 64 + ((ig * 16 + ii) ^ f)] * kvv;
    }
#pragma unroll
    for (int ii = 0; ii < 16; ii++) {
        int i = ig * 16 + ii;
        float yv = y[ii] / At[i];
        __nv_bfloat16 hh = __float2bfloat16_rn(yv);
        __nv_bfloat16 ll = __float2bfloat16_rn(yv - __bfloat162float(hh));
        long off = (long)(c * CS + i) * HID + h * HD + d;
        Yhi[off] = hh;
        Ylo[off] = ll;
    }
}

// ---------------------------------- launch ---------------------------------------
extern "C" void kernel_launch(void* const* d_in, const int* in_sizes, int n_in,
                              void* d_out, int out_size) {
    (void)in_sizes; (void)n_in; (void)out_size;
    const float* hs  = (const float*)d_in[0];
    const float* Wq  = (const float*)d_in[1];
    const float* Wk  = (const float*)d_in[2];
    const float* Wv  = (const float*)d_in[3];
    const float* Wo  = (const float*)d_in[4];
    const float* Wfq = (const float*)d_in[5];
    const float* Wfk = (const float*)d_in[6];
    float* out = (float*)d_out;

    float *FQp, *FKp, *Vp, *Sp, *KSp, *Pp, *POp;
    __nv_bfloat16 *Xhi, *Xlo, *Wqh, *Wql, *Wkh, *Wkl, *Wvh, *Wvl, *Woh, *Wol, *Yhi, *Ylo;
    cudaGetSymbolAddress((void**)&FQp, g_FQ);
    cudaGetSymbolAddress((void**)&FKp, g_FK);
    cudaGetSymbolAddress((void**)&Vp,  g_V);
    cudaGetSymbolAddress((void**)&Sp,  g_S);
    cudaGetSymbolAddress((void**)&KSp, g_KS);
    cudaGetSymbolAddress((void**)&Pp,  g_P);
    cudaGetSymbolAddress((void**)&POp, g_PO);
    cudaGetSymbolAddress((void**)&Xhi, g_Xhi);
    cudaGetSymbolAddress((void**)&Xlo, g_Xlo);
    cudaGetSymbolAddress((void**)&Wqh, g_Wqhi);
    cudaGetSymbolAddress((void**)&Wql, g_Wqlo);
    cudaGetSymbolAddress((void**)&Wkh, g_Wkhi);
    cudaGetSymbolAddress((void**)&Wkl, g_Wklo);
    cudaGetSymbolAddress((void**)&Wvh, g_Wvhi);
    cudaGetSymbolAddress((void**)&Wvl, g_Wvlo);
    cudaGetSymbolAddress((void**)&Woh, g_Wohi);
    cudaGetSymbolAddress((void**)&Wol, g_Wolo);
    cudaGetSymbolAddress((void**)&Yhi, g_Yhi);
    cudaGetSymbolAddress((void**)&Ylo, g_Ylo);

    cudaFuncSetAttribute(gemm_bf16x3, cudaFuncAttributeMaxDynamicSharedMemorySize, GEMM_SMEM);
    cudaFuncSetAttribute(featsum_kernel, cudaFuncAttributeMaxDynamicSharedMemorySize, FS_SMEM);

    split_all<<<(PLANE + 4 * HID * HID) / 2048, 256>>>(
        hs, Wq, Wk, Wv, Wo, Xhi, Xlo, Wqh, Wql, Wkh, Wkl, Wvh, Wvl, Woh, Wol);

    gemm_bf16x3<<<dim3(48, 8, 3), 256, GEMM_SMEM>>>(Xhi, Xlo, Wqh, Wql, Wkh, Wkl, Wvh, Wvl, Pp);

    featsum_kernel<<<dim3(NC, NH), 256, FS_SMEM>>>(Pp, Wfq, Wfk, FQp, FKp, Vp, Sp, KSp);

    prefix_kernel<<<512, 256>>>(Sp, KSp);

    chunkout_kernel<<<dim3(NC, NH), 256>>>(FQp, FKp, Vp, Sp, KSp, Yhi, Ylo);

    gemm_bf16x3<<<dim3(16, 8, 2), 256, GEMM_SMEM>>>(Yhi, Ylo, Woh, Wol, Woh, Wol, Woh, Wol, POp);

    combine1<<<PLANE / 1024, 256>>>((const float4*)POp, (const float4*)(POp + PLANE),
                                    (float4*)out);
}

// round 15
// speedup vs baseline: 1.0487x; 1.0487x over previous
#include <cuda_runtime.h>
#include <cuda_bf16.h>
#include <cstdint>

#define L_SEQ 1024
#define HID   2048
#define NH    32
#define HD    64
#define FD    64
#define NC    16
#define CS    64
#define GK    2048
#define GN    2048
#define PLANE (L_SEQ * HID)

// ---------------- scratch (device globals: no allocation allowed) ----------------
__device__ float g_FQ[NH * L_SEQ * FD];
__device__ float g_FK[NH * L_SEQ * FD];
__device__ float g_S [NH * NC * FD * HD];
__device__ float g_KS[NH * NC * FD];
__device__ float g_P [9 * PLANE];   // QKV split-K3 partials
__device__ float g_PO[2 * PLANE];   // Wo split-K2 partials

__device__ __nv_bfloat16 g_Xhi [PLANE];
__device__ __nv_bfloat16 g_Xlo [PLANE];
__device__ __nv_bfloat16 g_Wqhi[HID * HID];
__device__ __nv_bfloat16 g_Wqlo[HID * HID];
__device__ __nv_bfloat16 g_Wkhi[HID * HID];
__device__ __nv_bfloat16 g_Wklo[HID * HID];
__device__ __nv_bfloat16 g_Wvhi[HID * HID];
__device__ __nv_bfloat16 g_Wvlo[HID * HID];
__device__ __nv_bfloat16 g_Wohi[HID * HID];
__device__ __nv_bfloat16 g_Wolo[HID * HID];
__device__ __nv_bfloat16 g_Yhi [PLANE];
__device__ __nv_bfloat16 g_Ylo [PLANE];

// =============================== helpers ==========================================
__device__ __forceinline__ uint32_t smem_u32(const void* p) {
    uint32_t a;
    asm("{ .reg .u64 t; cvta.to.shared.u64 t, %1; cvt.u32.u64 %0, t; }" : "=r"(a) : "l"(p));
    return a;
}
__device__ __forceinline__ void ldsm4(uint32_t& r0, uint32_t& r1, uint32_t& r2, uint32_t& r3,
                                      uint32_t addr) {
    asm volatile("ldmatrix.sync.aligned.m8n8.x4.shared.b16 {%0,%1,%2,%3}, [%4];"
                 : "=r"(r0), "=r"(r1), "=r"(r2), "=r"(r3) : "r"(addr));
}
__device__ __forceinline__ void mma16816(float* c, const uint32_t* a, const uint32_t* b) {
    asm volatile(
        "mma.sync.aligned.m16n8k16.row.col.f32.bf16.bf16.f32 "
        "{%0,%1,%2,%3}, {%4,%5,%6,%7}, {%8,%9}, {%0,%1,%2,%3};"
        : "+f"(c[0]), "+f"(c[1]), "+f"(c[2]), "+f"(c[3])
        : "r"(a[0]), "r"(a[1]), "r"(a[2]), "r"(a[3]), "r"(b[0]), "r"(b[1]));
}
#define CP16(dst, src) \
    asm volatile("cp.async.cg.shared.global [%0], [%1], 16;" :: "r"(dst), "l"(src) : "memory")

__device__ __forceinline__ void split4(float4 v, uint2& hp, uint2& lp) {
    __nv_bfloat16 h0 = __float2bfloat16_rn(v.x);
    __nv_bfloat16 h1 = __float2bfloat16_rn(v.y);
    __nv_bfloat16 h2 = __float2bfloat16_rn(v.z);
    __nv_bfloat16 h3 = __float2bfloat16_rn(v.w);
    __nv_bfloat16 l0 = __float2bfloat16_rn(v.x - __bfloat162float(h0));
    __nv_bfloat16 l1 = __float2bfloat16_rn(v.y - __bfloat162float(h1));
    __nv_bfloat16 l2 = __float2bfloat16_rn(v.z - __bfloat162float(h2));
    __nv_bfloat16 l3 = __float2bfloat16_rn(v.w - __bfloat162float(h3));
    hp.x = (uint32_t)__bfloat16_as_ushort(h0) | ((uint32_t)__bfloat16_as_ushort(h1) << 16);
    hp.y = (uint32_t)__bfloat16_as_ushort(h2) | ((uint32_t)__bfloat16_as_ushort(h3) << 16);
    lp.x = (uint32_t)__bfloat16_as_ushort(l0) | ((uint32_t)__bfloat16_as_ushort(l1) << 16);
    lp.y = (uint32_t)__bfloat16_as_ushort(l2) | ((uint32_t)__bfloat16_as_ushort(l3) << 16);
}

__device__ __forceinline__ void split8_store(const float* s, __nv_bfloat16* hi,
                                             __nv_bfloat16* lo, long loc) {
    float4 v0 = *(const float4*)(s + loc);
    float4 v1 = *(const float4*)(s + loc + 4);
    uint2 h0, l0, h1, l1;
    split4(v0, h0, l0);
    split4(v1, h1, l1);
    uint4 ho, lv;
    ho.x = h0.x; ho.y = h0.y; ho.z = h1.x; ho.w = h1.y;
    lv.x = l0.x; lv.y = l0.y; lv.z = l1.x; lv.w = l1.y;
    *(uint4*)(hi + loc) = ho;
    *(uint4*)(lo + loc) = lv;
}

// ---------------- fused split: X + 4 weights in one launch ------------------------
__global__ __launch_bounds__(256) void split_all(
    const float* __restrict__ X,  const float* __restrict__ Wq,
    const float* __restrict__ Wk, const float* __restrict__ Wv,
    const float* __restrict__ Wo,
    __nv_bfloat16* __restrict__ Xhi, __nv_bfloat16* __restrict__ Xlo,
    __nv_bfloat16* __restrict__ Wqh, __nv_bfloat16* __restrict__ Wql,
    __nv_bfloat16* __restrict__ Wkh, __nv_bfloat16* __restrict__ Wkl,
    __nv_bfloat16* __restrict__ Wvh, __nv_bfloat16* __restrict__ Wvl,
    __nv_bfloat16* __restrict__ Woh, __nv_bfloat16* __restrict__ Wol) {
    long off = ((long)blockIdx.x * 256 + threadIdx.x) * 8;
    const float* s;
    __nv_bfloat16 *hi, *lo;
    long loc;
    const long W = (long)HID * HID;
    if (off < PLANE)            { s = X;  hi = Xhi; lo = Xlo; loc = off; }
    else if (off < PLANE + W)   { s = Wq; hi = Wqh; lo = Wql; loc = off - PLANE; }
    else if (off < PLANE + 2*W) { s = Wk; hi = Wkh; lo = Wkl; loc = off - PLANE - W; }
    else if (off < PLANE + 3*W) { s = Wv; hi = Wvh; lo = Wvl; loc = off - PLANE - 2*W; }
    else                        { s = Wo; hi = Woh; lo = Wol; loc = off - PLANE - 3*W; }
    split8_store(s, hi, lo, loc);
}

// ---------------- combine for Wo split-K ------------------------------------------
__global__ __launch_bounds__(256) void combine1(const float4* __restrict__ a,
                                                const float4* __restrict__ b,
                                                float4* __restrict__ dst) {
    int i = blockIdx.x * 256 + threadIdx.x;
    float4 va = a[i], vb = b[i];
    dst[i] = make_float4(va.x + vb.x, va.y + vb.y, va.z + vb.z, va.w + vb.w);
}

// ======= bf16x3 HMMA GEMM: 128x128x32 tile, 2-stage cp.async, split-K(gridDim.z) ==
#define ROWB   80
#define TILEB  (128 * ROWB)
#define STAGEB (4 * TILEB)
#define GEMM_SMEM (2 * STAGEB)

__device__ __forceinline__ void issue_chunk(
    uint32_t stg, const __nv_bfloat16* Ahi, const __nv_bfloat16* Alo,
    const __nv_bfloat16* Bhi, const __nv_bfloat16* Blo,
    int m0, int n0, int k0, int t) {
#pragma unroll
    for (int j = 0; j < 2; j++) {
        int idx = t + 256 * j;
        int row = idx >> 2, c = idx & 3;
        uint32_t dof = (uint32_t)(row * ROWB + c * 16);
        long aoff = (long)(m0 + row) * GK + k0 + c * 8;
        long boff = (long)(n0 + row) * GK + k0 + c * 8;
        CP16(stg + dof,             Ahi + aoff);
        CP16(stg + TILEB + dof,     Alo + aoff);
        CP16(stg + 2 * TILEB + dof, Bhi + boff);
        CP16(stg + 3 * TILEB + dof, Blo + boff);
    }
    asm volatile("cp.async.commit_group;" ::: "memory");
}

__global__ __launch_bounds__(256, 2) void gemm_bf16x3(
    const __nv_bfloat16* __restrict__ Ahi, const __nv_bfloat16* __restrict__ Alo,
    const __nv_bfloat16* __restrict__ Bhi0, const __nv_bfloat16* __restrict__ Blo0,
    const __nv_bfloat16* __restrict__ Bhi1, const __nv_bfloat16* __restrict__ Blo1,
    const __nv_bfloat16* __restrict__ Bhi2, const __nv_bfloat16* __restrict__ Blo2,
    float* __restrict__ Pout) {
    extern __shared__ char smem[];
    const uint32_t sb = smem_u32(smem);

    const int t = threadIdx.x, wid = t >> 5, lane = t & 31;
    const int wsel  = blockIdx.x >> 4;
    const int kslot = blockIdx.z;
    const int nz    = gridDim.z;
    const int n0 = (blockIdx.x & 15) * 128;
    const int m0 = blockIdx.y * 128;
    const __nv_bfloat16* Bhi = (wsel == 0) ? Bhi0 : (wsel == 1) ? Bhi1 : Bhi2;
    const __nv_bfloat16* Blo = (wsel == 0) ? Blo0 : (wsel == 1) ? Blo1 : Blo2;
    float* C = Pout + (long)(wsel * nz + kslot) * PLANE;

    const int per = 64 / nz, rem = 64 % nz;
    const int cstart = kslot * per + (kslot < rem ? kslot : rem);
    const int NIT    = per + (kslot < rem ? 1 : 0);
    const int kb     = cstart * 32;

    const int wm0 = (wid >> 2) * 64;
    const int wn0 = (wid & 3) * 32;
    const int g  = lane >> 3;
    const int lr = lane & 7;

    float acc[4][4][4];
#pragma unroll
    for (int i = 0; i < 4; i++)
#pragma unroll
        for (int j = 0; j < 4; j++)
#pragma unroll
            for (int k = 0; k < 4; k++) acc[i][j][k] = 0.f;

    issue_chunk(sb,          Ahi, Alo, Bhi, Blo, m0, n0, kb,      t);
    issue_chunk(sb + STAGEB, Ahi, Alo, Bhi, Blo, m0, n0, kb + 32, t);

    for (int it = 0; it < NIT; it++) {
        if (it < NIT - 1) asm volatile("cp.async.wait_group 1;" ::: "memory");
        else              asm volatile("cp.async.wait_group 0;" ::: "memory");
        __syncthreads();

        const uint32_t ahi = sb + (it & 1) * STAGEB;
        const uint32_t alo = ahi + TILEB;
        const uint32_t bhi = ahi + 2 * TILEB;
        const uint32_t blo = ahi + 3 * TILEB;

#pragma unroll
        for (int ks = 0; ks < 2; ks++) {
            uint32_t bh[4][2], bl[4][2];
#pragma unroll
            for (int nt2 = 0; nt2 < 2; nt2++) {
                int row = wn0 + nt2 * 16 + (g >> 1) * 8 + lr;
                int kc  = ks * 16 + (g & 1) * 8;
                uint32_t off = (uint32_t)(row * ROWB + kc * 2);
                ldsm4(bh[nt2 * 2][0], bh[nt2 * 2][1], bh[nt2 * 2 + 1][0], bh[nt2 * 2 + 1][1],
                      bhi + off);
                ldsm4(bl[nt2 * 2][0], bl[nt2 * 2][1], bl[nt2 * 2 + 1][0], bl[nt2 * 2 + 1][1],
                      blo + off);
            }
#pragma unroll
            for (int mt = 0; mt < 4; mt++) {
                int row = wm0 + mt * 16 + (g & 1) * 8 + lr;
                int kc  = ks * 16 + (g >> 1) * 8;
                uint32_t off = (uint32_t)(row * ROWB + kc * 2);
                uint32_t ah[4], al[4];
                ldsm4(ah[0], ah[1], ah[2], ah[3], ahi + off);
                ldsm4(al[0], al[1], al[2], al[3], alo + off);
#pragma unroll
                for (int nt = 0; nt < 4; nt++) mma16816(acc[mt][nt], ah, bh[nt]);
#pragma unroll
                for (int nt = 0; nt < 4; nt++) mma16816(acc[mt][nt], ah, bl[nt]);
#pragma unroll
                for (int nt = 0; nt < 4; nt++) mma16816(acc[mt][nt], al, bh[nt]);
            }
        }
        __syncthreads();
        if (it + 2 < NIT)
            issue_chunk(sb + (it & 1) * STAGEB, Ahi, Alo, Bhi, Blo, m0, n0,
                        kb + (it + 2) * 32, t);
    }

    const int gid = lane >> 2, tig = lane & 3;
#pragma unroll
    for (int mt = 0; mt < 4; mt++) {
#pragma unroll
        for (int nt = 0; nt < 4; nt++) {
            int row = m0 + wm0 + mt * 16 + gid;
            int col = n0 + wn0 + nt * 8 + tig * 2;
            *(float2*)(C + (long)row * GN + col) =
                make_float2(acc[mt][nt][0], acc[mt][nt][1]);
            *(float2*)(C + (long)(row + 8) * GN + col) =
                make_float2(acc[mt][nt][2], acc[mt][nt][3]);
        }
    }
}

// ===== fused feature+chunksum per (chunk, head): fq->FQ, fk->FK+smem, S/KS ========
#define FS_SMEM ((4096 + 4352 + 4096) * 4)

__device__ __forceinline__ void fs_feature_phase(
    float* qs, float* wt, float* fks, const float* p0, const float* p1, const float* p2,
    const float* Wf, float* dst_g, int l0, int h, int t, bool keep) {
#pragma unroll
    for (int r = 0; r < 16; r++) {
        int e = t + 256 * r;
        int row = e >> 6, col = e & 63;
        long idx = (long)(l0 + row) * HID + h * HD + col;
        qs[e] = p0[idx] + p1[idx] + p2[idx];
        wt[col * 68 + row] = Wf[e];
    }
    __syncthreads();

    int warp = t >> 5, lane = t & 31;
    float z0[8], z1[8];
#pragma unroll
    for (int r = 0; r < 8; r++) { z0[r] = 0.f; z1[r] = 0.f; }
#pragma unroll 4
    for (int d4 = 0; d4 < 64; d4 += 4) {
        float4 qv[8];
#pragma unroll
        for (int r = 0; r < 8; r++)
            qv[r] = *(const float4*)&qs[(warp * 8 + r) * 64 + d4];
        float4 w0v = *(const float4*)&wt[lane * 68 + d4];
        float4 w1v = *(const float4*)&wt[(lane + 32) * 68 + d4];
#pragma unroll
        for (int j = 0; j < 4; j++) {
            float w0 = (&w0v.x)[j];
            float w1 = (&w1v.x)[j];
#pragma unroll
            for (int r = 0; r < 8; r++) {
                float qj = (&qv[r].x)[j];
                z0[r] += qj * w0;
                z1[r] += qj * w1;
            }
        }
    }
#pragma unroll
    for (int r = 0; r < 8; r++) {
        float m = fmaxf(z0[r], z1[r]);
#pragma unroll
        for (int o = 16; o > 0; o >>= 1) m = fmaxf(m, __shfl_xor_sync(0xffffffffu, m, o));
        float e0 = expf(z0[r] - m), e1 = expf(z1[r] - m);
        float s = e0 + e1;
#pragma unroll
        for (int o = 16; o > 0; o >>= 1) s += __shfl_xor_sync(0xffffffffu, s, o);
        float inv = 1.f / s;
        int lr2 = warp * 8 + r;
        float f0 = e0 * inv, f1 = e1 * inv;
        dst_g[(long)(l0 + lr2) * FD + lane]      = f0;
        dst_g[(long)(l0 + lr2) * FD + lane + 32] = f1;
        if (keep) {
            fks[lr2 * 64 + lane]      = f0;
            fks[lr2 * 64 + lane + 32] = f1;
        }
    }
}

__global__ __launch_bounds__(256) void featsum_kernel(
    const float* __restrict__ P,
    const float* __restrict__ Wfq, const float* __restrict__ Wfk,
    float* __restrict__ FQ, float* __restrict__ FK,
    float* __restrict__ S, float* __restrict__ KS) {
    extern __shared__ float sm[];
    float* qs  = sm;
    float* wt  = sm + 4096;
    float* fks = sm + 4096 + 4352;

    int c = blockIdx.x, h = blockIdx.y;
    int l0 = c * CS;
    int t = threadIdx.x;

    fs_feature_phase(qs, wt, fks, P, P + PLANE, P + 2L * PLANE,
                     Wfq + (long)h * HD * FD, FQ + (long)h * L_SEQ * FD, l0, h, t, false);
    __syncthreads();

    fs_feature_phase(qs, wt, fks, P + 3L * PLANE, P + 4L * PLANE, P + 5L * PLANE,
                     Wfk + (long)h * HD * FD, FK + (long)h * L_SEQ * FD, l0, h, t, true);
    __syncthreads();

    const float* v0 = P + 6L * PLANE;
    const float* v1 = v0 + PLANE;
    const float* v2 = v1 + PLANE;
#pragma unroll
    for (int r = 0; r < 16; r++) {
        int e = t + 256 * r;
        int row = e >> 6, col = e & 63;
        long vi = (long)(l0 + row) * HID + h * HD + col;
        qs[e] = v0[vi] + v1[vi] + v2[vi];
    }
    __syncthreads();

    int d = t & 63, fg = t >> 6;
    float acc[16];
#pragma unroll
    for (int ff = 0; ff < 16; ff++) acc[ff] = 0.f;
    for (int l = 0; l < 64; l++) {
        float vv = qs[l * 64 + d];
#pragma unroll
        for (int ff = 0; ff < 16; ff++)
            acc[ff] += fks[l * 64 + fg * 16 + ff] * vv;
    }
    float* Sout = S + (long)(h * NC + c) * (FD * HD);
#pragma unroll
    for (int ff = 0; ff < 16; ff++)
        Sout[(fg * 16 + ff) * 64 + d] = acc[ff];

    if (t < 64) {
        float s = 0.f;
        for (int l = 0; l < 64; l++) s += fks[l * 64 + t];
        KS[(long)(h * NC + c) * FD + t] = s;
    }
}

// ---------------- exclusive prefix over chunks ------------------------------------
__global__ __launch_bounds__(256) void prefix_kernel(float* __restrict__ S,
                                                     float* __restrict__ KS) {
    int id = blockIdx.x * 256 + threadIdx.x;
    int h = id >> 12, e = id & 4095;
    float* base = S + (long)h * (NC * FD * HD) + e;
    float v[NC];
#pragma unroll
    for (int c = 0; c < NC; c++) v[c] = base[c * (FD * HD)];
    float run = 0.f;
#pragma unroll
    for (int c = 0; c < NC; c++) { float tmp = v[c]; base[c * (FD * HD)] = run; run += tmp; }

    if (id < NH * FD) {
        int h2 = id >> 6, f = id & 63;
        float* kb = KS + (long)h2 * (NC * FD) + f;
        float kv[NC];
#pragma unroll
        for (int c = 0; c < NC; c++) kv[c] = kb[c * FD];
        float kr = 0.f;
#pragma unroll
        for (int c = 0; c < NC; c++) { float tmp = kv[c]; kb[c * FD] = kr; kr += tmp; }
    }
}

// ---- per-chunk output (V from 3 partials; register-prefetched across phases) -----
__global__ __launch_bounds__(256) void chunkout_kernel(
    const float* __restrict__ FQ, const float* __restrict__ FK,
    const float* __restrict__ P, const float* __restrict__ S,
    const float* __restrict__ KS,
    __nv_bfloat16* __restrict__ Yhi, __nv_bfloat16* __restrict__ Ylo) {
    __shared__ float fqT[4096];
    __shared__ float buf[4096];
    __shared__ float At[4096];

    int c = blockIdx.x, h = blockIdx.y;
    int t = threadIdx.x, lane = t & 31;

    const float* fqg = FQ + (long)(h * L_SEQ + c * CS) * FD;
    const float* fkg = FK + (long)(h * L_SEQ + c * CS) * FD;

#pragma unroll
    for (int r = 0; r < 16; r++) {
        int e = t + 256 * r;
        int i = e >> 6, f = e & 63;
        fqT[f * 64 + (i ^ f)] = fqg[e];
        buf[f * 64 + (i ^ f)] = fkg[e];
    }

    // prefetch V partials into registers (loads overlap P1 compute)
    const float* v0 = P + 6L * PLANE + (long)(c * CS) * HID + h * HD;
    const float* v1 = v0 + PLANE;
    const float* v2 = v1 + PLANE;
    float vp[16];
#pragma unroll
    for (int r = 0; r < 16; r++) {
        int e = t + 256 * r;
        long vi = (long)(e >> 6) * HID + (e & 63);
        vp[r] = v0[vi] + v1[vi] + v2[vi];
    }
    __syncthreads();

    // P1: masked score matrix A^T
    {
        int i = t & 63, jg = t >> 6;
        float a[16];
#pragma unroll
        for (int jj = 0; jj < 16; jj++) a[jj] = 0.f;
        for (int f = 0; f < 64; f++) {
            float qv = fqT[f * 64 + (i ^ f)];
#pragma unroll
            for (int jj = 0; jj < 16; jj++) {
                int j = jg * 16 + jj;
                a[jj] += qv * buf[f * 64 + (j ^ f)];
            }
        }
#pragma unroll
        for (int jj = 0; jj < 16; jj++) {
            int j = jg * 16 + jj;
            At[j * 64 + i] = (j <= i) ? a[jj] : 0.f;
        }
    }
    __syncthreads();

    // commit prefetched V to smem; prefetch S into registers (overlaps P2)
#pragma unroll
    for (int r = 0; r < 16; r++) buf[t + 256 * r] = vp[r];
    const float* sg = S + (long)(h * NC + c) * (FD * HD);
    float sp[16];
#pragma unroll
    for (int r = 0; r < 16; r++) sp[r] = sg[t + 256 * r];
    __syncthreads();

    // P2: y_intra + denominator
    int d = t & 63, ig = t >> 6;
    float y[16];
#pragma unroll
    for (int ii = 0; ii < 16; ii++) y[ii] = 0.f;
    for (int j = 0; j < 64; j++) {
        float vv = buf[j * 64 + d];
#pragma unroll
        for (int ii = 0; ii < 16; ii++)
            y[ii] += At[j * 64 + ig * 16 + ii] * vv;
    }
    float ds = 0.f;
    if (t < 64) {
        ds = 1e-12f;
        const float* kb = KS + (long)(h * NC + c) * FD;
        float kp0 = kb[lane], kp1 = kb[lane + 32];
        for (int f = 0; f < 32; f++) {
            ds += fqT[f * 64 + (t ^ f)] * __shfl_sync(0xffffffffu, kp0, f);
            ds += fqT[(f + 32) * 64 + (t ^ (f + 32))] * __shfl_sync(0xffffffffu, kp1, f);
        }
        for (int j = 0; j < 64; j++) ds += At[j * 64 + t];
    }
    __syncthreads();

    // commit prefetched S; stash denom
#pragma unroll
    for (int r = 0; r < 16; r++) buf[t + 256 * r] = sp[r];
    if (t < 64) At[t] = ds;
    __syncthreads();

    // P3: inter-chunk contribution + divide + split-store
    for (int f = 0; f < 64; f++) {
        float kvv = buf[f * 64 + d];
#pragma unroll
        for (int ii = 0; ii < 16; ii++)
            y[ii] += fqT[f * 64 + ((ig * 16 + ii) ^ f)] * kvv;
    }
#pragma unroll
    for (int ii = 0; ii < 16; ii++) {
        int i = ig * 16 + ii;
        float yv = y[ii] / At[i];
        __nv_bfloat16 hh = __float2bfloat16_rn(yv);
        __nv_bfloat16 ll = __float2bfloat16_rn(yv - __bfloat162float(hh));
        long off = (long)(c * CS + i) * HID + h * HD + d;
        Yhi[off] = hh;
        Ylo[off] = ll;
    }
}

// ---------------------------------- launch ---------------------------------------
extern "C" void kernel_launch(void* const* d_in, const int* in_sizes, int n_in,
                              void* d_out, int out_size) {
    (void)in_sizes; (void)n_in; (void)out_size;
    const float* hs  = (const float*)d_in[0];
    const float* Wq  = (const float*)d_in[1];
    const float* Wk  = (const float*)d_in[2];
    const float* Wv  = (const float*)d_in[3];
    const float* Wo  = (const float*)d_in[4];
    const float* Wfq = (const float*)d_in[5];
    const float* Wfk = (const float*)d_in[6];
    float* out = (float*)d_out;

    float *FQp, *FKp, *Sp, *KSp, *Pp, *POp;
    __nv_bfloat16 *Xhi, *Xlo, *Wqh, *Wql, *Wkh, *Wkl, *Wvh, *Wvl, *Woh, *Wol, *Yhi, *Ylo;
    cudaGetSymbolAddress((void**)&FQp, g_FQ);
    cudaGetSymbolAddress((void**)&FKp, g_FK);
    cudaGetSymbolAddress((void**)&Sp,  g_S);
    cudaGetSymbolAddress((void**)&KSp, g_KS);
    cudaGetSymbolAddress((void**)&Pp,  g_P);
    cudaGetSymbolAddress((void**)&POp, g_PO);
    cudaGetSymbolAddress((void**)&Xhi, g_Xhi);
    cudaGetSymbolAddress((void**)&Xlo, g_Xlo);
    cudaGetSymbolAddress((void**)&Wqh, g_Wqhi);
    cudaGetSymbolAddress((void**)&Wql, g_Wqlo);
    cudaGetSymbolAddress((void**)&Wkh, g_Wkhi);
    cudaGetSymbolAddress((void**)&Wkl, g_Wklo);
    cudaGetSymbolAddress((void**)&Wvh, g_Wvhi);
    cudaGetSymbolAddress((void**)&Wvl, g_Wvlo);
    cudaGetSymbolAddress((void**)&Woh, g_Wohi);
    cudaGetSymbolAddress((void**)&Wol, g_Wolo);
    cudaGetSymbolAddress((void**)&Yhi, g_Yhi);
    cudaGetSymbolAddress((void**)&Ylo, g_Ylo);

    cudaFuncSetAttribute(gemm_bf16x3, cudaFuncAttributeMaxDynamicSharedMemorySize, GEMM_SMEM);
    cudaFuncSetAttribute(featsum_kernel, cudaFuncAttributeMaxDynamicSharedMemorySize, FS_SMEM);

    split_all<<<(PLANE + 4 * HID * HID) / 2048, 256>>>(
        hs, Wq, Wk, Wv, Wo, Xhi, Xlo, Wqh, Wql, Wkh, Wkl, Wvh, Wvl, Woh, Wol);

    gemm_bf16x3<<<dim3(48, 8, 3), 256, GEMM_SMEM>>>(Xhi, Xlo, Wqh, Wql, Wkh, Wkl, Wvh, Wvl, Pp);

    featsum_kernel<<<dim3(NC, NH), 256, FS_SMEM>>>(Pp, Wfq, Wfk, FQp, FKp, Sp, KSp);

    prefix_kernel<<<512, 256>>>(Sp, KSp);

    chunkout_kernel<<<dim3(NC, NH), 256>>>(FQp, FKp, Pp, Sp, KSp, Yhi, Ylo);

    gemm_bf16x3<<<dim3(16, 8, 2), 256, GEMM_SMEM>>>(Yhi, Ylo, Woh, Wol, Woh, Wol, Woh, Wol, POp);

    combine1<<<PLANE / 1024, 256>>>((const float4*)POp, (const float4*)(POp + PLANE),
                                    (float4*)out);
}